// round 2
// baseline (speedup 1.0000x reference)
#include <cuda_runtime.h>
#include <math.h>

#define B_ROWS 32768
#define OBS    512
#define H1D    1024
#define H2D    1024
#define ACT    64
#define NOUT   (2*ACT)

// ---------------- device scratch (static: no allocations allowed) ----------------
__device__ float g_W1q[H1D*OBS];
__device__ float g_W2q[H2D*H1D];
__device__ float g_W3q[NOUT*H2D];
__device__ float g_b1q[H1D];
__device__ float g_b2q[H2D];
__device__ float g_b3q[NOUT];
__device__ unsigned g_maxbits[3];
__device__ float g_h1[(size_t)B_ROWS*H1D];
__device__ float g_h2[(size_t)B_ROWS*H2D];
__device__ float g_net[(size_t)B_ROWS*NOUT];

// ---------------- quantization prep ----------------
__global__ void zero_max_kernel() {
    if (threadIdx.x < 3) g_maxbits[threadIdx.x] = 0u;
}

__global__ void maxabs_kernel(const float* __restrict__ W, int n, int slot) {
    unsigned m = 0u;
    for (int i = blockIdx.x*blockDim.x + threadIdx.x; i < n; i += gridDim.x*blockDim.x)
        m = max(m, __float_as_uint(fabsf(W[i])));
    #pragma unroll
    for (int o = 16; o; o >>= 1) m = max(m, __shfl_xor_sync(0xffffffffu, m, o));
    __shared__ unsigned sm[32];
    int lane = threadIdx.x & 31, wid = threadIdx.x >> 5;
    if (lane == 0) sm[wid] = m;
    __syncthreads();
    if (wid == 0) {
        m = (lane < (int)(blockDim.x >> 5)) ? sm[lane] : 0u;
        #pragma unroll
        for (int o = 16; o; o >>= 1) m = max(m, __shfl_xor_sync(0xffffffffu, m, o));
        if (lane == 0) atomicMax(&g_maxbits[slot], m);
    }
}

__device__ __forceinline__ float qw(float w, float s) {
    // clip(round_half_even(w/s), -127, 127) * s   — IEEE division to match JAX exactly
    float r = rintf(__fdiv_rn(w, s));
    r = fminf(fmaxf(r, -127.0f), 127.0f);
    return r * s;
}
__device__ __forceinline__ float qb(float b, float s) {
    float r = rintf(__fdiv_rn(b, s));
    r = fminf(fmaxf(r, -128.0f), 127.0f);
    return r * s;
}

__global__ void quant_all_kernel(const float* __restrict__ W1, const float* __restrict__ b1,
                                 const float* __restrict__ W2, const float* __restrict__ b2,
                                 const float* __restrict__ W3, const float* __restrict__ b3,
                                 float s_in) {
    const float ws1 = __fdiv_rn(__uint_as_float(g_maxbits[0]), 127.0f);
    const float ws2 = __fdiv_rn(__uint_as_float(g_maxbits[1]), 127.0f);
    const float ws3 = __fdiv_rn(__uint_as_float(g_maxbits[2]), 127.0f);
    const float sb1 = s_in * ws1;          // fp32 chain, matching reference
    const float sb2 = sb1 * ws2;
    const float sb3 = sb2 * ws3;
    const int tid = blockIdx.x*blockDim.x + threadIdx.x;
    const int stride = gridDim.x*blockDim.x;
    for (int i = tid; i < H1D*OBS;  i += stride) g_W1q[i] = qw(W1[i], ws1);
    for (int i = tid; i < H2D*H1D;  i += stride) g_W2q[i] = qw(W2[i], ws2);
    for (int i = tid; i < NOUT*H2D; i += stride) g_W3q[i] = qw(W3[i], ws3);
    for (int i = tid; i < H1D;  i += stride) g_b1q[i] = qb(b1[i], sb1);
    for (int i = tid; i < H2D;  i += stride) g_b2q[i] = qb(b2[i], sb2);
    for (int i = tid; i < NOUT; i += stride) g_b3q[i] = qb(b3[i], sb3);
}

// ---------------- fused GEMM + bias + optional ReLU ----------------
// C[M,N] = act( A[M,K] (row-major, scaled by aScale) @ W[N,K]^T + bias[N] )
#define BM 128
#define BN 128
#define BK 16

__global__ __launch_bounds__(256, 2)
void gemm_bias_act(const float* __restrict__ A, float aScale,
                   const float* __restrict__ W, const float* __restrict__ bias,
                   float* __restrict__ C, int M, int N, int K, int doRelu) {
    __shared__ float As[BK][BM+4];
    __shared__ float Bs[BK][BN+4];

    const int tid = threadIdx.x;
    const int bm  = blockIdx.y * BM;
    const int bn  = blockIdx.x * BN;
    const int tx  = tid & 15;        // 16 thread cols
    const int ty  = tid >> 4;        // 16 thread rows
    const int lr  = tid >> 2;        // loader row 0..63
    const int lc  = (tid & 3) << 2;  // loader col 0,4,8,12

    float acc[8][8];
    #pragma unroll
    for (int i = 0; i < 8; i++)
        #pragma unroll
        for (int j = 0; j < 8; j++) acc[i][j] = 0.0f;

    const float* Aptr = A + (long)bm * K;
    const float* Wptr = W + (long)bn * K;

    for (int k0 = 0; k0 < K; k0 += BK) {
        #pragma unroll
        for (int h = 0; h < 2; h++) {
            int r = lr + h*64;
            float4 va = *(const float4*)(Aptr + (long)r*K + k0 + lc);
            As[lc+0][r] = va.x * aScale;
            As[lc+1][r] = va.y * aScale;
            As[lc+2][r] = va.z * aScale;
            As[lc+3][r] = va.w * aScale;
            float4 vw = *(const float4*)(Wptr + (long)r*K + k0 + lc);
            Bs[lc+0][r] = vw.x;
            Bs[lc+1][r] = vw.y;
            Bs[lc+2][r] = vw.z;
            Bs[lc+3][r] = vw.w;
        }
        __syncthreads();

        #pragma unroll
        for (int kk = 0; kk < BK; kk++) {
            float a[8], b[8];
            *(float4*)&a[0] = *(const float4*)&As[kk][ty*4];
            *(float4*)&a[4] = *(const float4*)&As[kk][64 + ty*4];
            *(float4*)&b[0] = *(const float4*)&Bs[kk][tx*4];
            *(float4*)&b[4] = *(const float4*)&Bs[kk][64 + tx*4];
            #pragma unroll
            for (int i = 0; i < 8; i++)
                #pragma unroll
                for (int j = 0; j < 8; j++)
                    acc[i][j] = fmaf(a[i], b[j], acc[i][j]);
        }
        __syncthreads();
    }

    #pragma unroll
    for (int i = 0; i < 8; i++) {
        int r = bm + ((i < 4) ? (ty*4 + i) : (64 + ty*4 + (i-4)));
        #pragma unroll
        for (int jh = 0; jh < 2; jh++) {
            int c0 = bn + jh*64 + tx*4;
            float4 o;
            o.x = acc[i][jh*4+0] + bias[c0+0];
            o.y = acc[i][jh*4+1] + bias[c0+1];
            o.z = acc[i][jh*4+2] + bias[c0+2];
            o.w = acc[i][jh*4+3] + bias[c0+3];
            if (doRelu) {
                o.x = fmaxf(o.x, 0.0f); o.y = fmaxf(o.y, 0.0f);
                o.z = fmaxf(o.z, 0.0f); o.w = fmaxf(o.w, 0.0f);
            }
            *(float4*)(C + (long)r*N + c0) = o;
        }
    }
}

// ---------------- distribution epilogue: one warp per batch row ----------------
__global__ void epilogue_kernel(const float* __restrict__ eps,
                                float* __restrict__ outAction,
                                float* __restrict__ outLogp) {
    const int row  = blockIdx.x * (blockDim.x >> 5) + (threadIdx.x >> 5);
    const int lane = threadIdx.x & 31;
    if (row >= B_ROWS) return;
    const float* net = g_net + (long)row * NOUT;
    float s = 0.0f;
    #pragma unroll
    for (int h = 0; h < 2; h++) {
        int j = lane + h*32;
        float mu = net[j];
        float ls = fminf(fmaxf(net[ACT + j], -20.0f), 2.0f);
        float sd = expf(ls);
        float e  = eps[(long)row*ACT + j];
        float pi = fmaf(sd, e, mu);
        outAction[(long)row*ACT + j] = tanhf(pi);
        float z  = (pi - mu) / sd;
        float m2p = -2.0f * pi;
        float sp  = fmaxf(m2p, 0.0f) + log1pf(expf(-fabsf(m2p)));  // softplus(-2*pi)
        s += -0.5f*z*z - ls - 0.91893853320467274f               // -0.5*log(2*pi)
             - 2.0f*(0.69314718055994531f - pi - sp);            // tanh correction
    }
    #pragma unroll
    for (int o = 16; o; o >>= 1) s += __shfl_xor_sync(0xffffffffu, s, o);
    if (lane == 0 && outLogp) outLogp[row] = s;
}

// ---------------- launcher ----------------
extern "C" void kernel_launch(void* const* d_in, const int* in_sizes, int n_in,
                              void* d_out, int out_size) {
    const float* obs = (const float*)d_in[0];
    const float* eps = (const float*)d_in[1];
    const float* W1  = (const float*)d_in[2];
    const float* b1  = (const float*)d_in[3];
    const float* W2  = (const float*)d_in[4];
    const float* b2  = (const float*)d_in[5];
    const float* W3  = (const float*)d_in[6];
    const float* b3  = (const float*)d_in[7];

    float* out = (float*)d_out;
    float* outAction = out;
    float* outLogp = (out_size >= B_ROWS*(ACT+1)) ? (out + (size_t)B_ROWS*ACT) : nullptr;

    const float S_IN = (float)(1.0/12000.0);
    const float F0   = (float)((1.0/12000.0) * (1.0/12000.0));  // input pre-scale

    float *pW1q, *pW2q, *pW3q, *pb1q, *pb2q, *pb3q, *ph1, *ph2, *pnet;
    cudaGetSymbolAddress((void**)&pW1q, g_W1q);
    cudaGetSymbolAddress((void**)&pW2q, g_W2q);
    cudaGetSymbolAddress((void**)&pW3q, g_W3q);
    cudaGetSymbolAddress((void**)&pb1q, g_b1q);
    cudaGetSymbolAddress((void**)&pb2q, g_b2q);
    cudaGetSymbolAddress((void**)&pb3q, g_b3q);
    cudaGetSymbolAddress((void**)&ph1,  g_h1);
    cudaGetSymbolAddress((void**)&ph2,  g_h2);
    cudaGetSymbolAddress((void**)&pnet, g_net);

    // 1) quantization prep
    zero_max_kernel<<<1, 32>>>();
    maxabs_kernel<<<256, 256>>>(W1, H1D*OBS, 0);
    maxabs_kernel<<<256, 256>>>(W2, H2D*H1D, 1);
    maxabs_kernel<<<64,  256>>>(W3, NOUT*H2D, 2);
    quant_all_kernel<<<512, 256>>>(W1, b1, W2, b2, W3, b3, S_IN);

    // 2) MLP
    dim3 g1(H1D/BN, B_ROWS/BM);
    gemm_bias_act<<<g1, 256>>>(obs, F0, pW1q, pb1q, ph1, B_ROWS, H1D, OBS, 1);
    dim3 g2(H2D/BN, B_ROWS/BM);
    gemm_bias_act<<<g2, 256>>>(ph1, 1.0f, pW2q, pb2q, ph2, B_ROWS, H2D, H1D, 1);
    dim3 g3(NOUT/BN, B_ROWS/BM);
    gemm_bias_act<<<g3, 256>>>(ph2, 1.0f, pW3q, pb3q, pnet, B_ROWS, NOUT, H2D, 0);

    // 3) squashed-Gaussian epilogue (8 rows per 256-thread block)
    epilogue_kernel<<<B_ROWS/8, 256>>>(eps, outAction, outLogp);
}

// round 4
// speedup vs baseline: 3.3505x; 3.3505x over previous
#include <cuda_runtime.h>
#include <cuda_bf16.h>
#include <math.h>
#include <stdint.h>

#define B_ROWS 32768
#define OBS    512
#define H1D    1024
#define H2D    1024
#define ACT    64
#define NOUT   (2*ACT)

// ---------------- device scratch (static: no allocations allowed) ----------------
__device__ __nv_bfloat16 g_W1r[H1D*OBS];     // integer-valued bf16 weights (exact)
__device__ __nv_bfloat16 g_W2r[H2D*H1D];
__device__ __nv_bfloat16 g_W3r[NOUT*H2D];
__device__ float g_b1q[H1D];
__device__ float g_b2q[H2D];
__device__ float g_b3q[NOUT];
__device__ float g_scales[3];
__device__ unsigned g_maxbits[3];
__device__ __nv_bfloat16 g_xhi[(size_t)B_ROWS*OBS];
__device__ __nv_bfloat16 g_xlo[(size_t)B_ROWS*OBS];
__device__ __nv_bfloat16 g_h1hi[(size_t)B_ROWS*H1D];
__device__ __nv_bfloat16 g_h1lo[(size_t)B_ROWS*H1D];
__device__ __nv_bfloat16 g_h2hi[(size_t)B_ROWS*H2D];
__device__ __nv_bfloat16 g_h2lo[(size_t)B_ROWS*H2D];
__device__ float g_net[(size_t)B_ROWS*NOUT];

// ---------------- PTX helpers (sm_103-safe subset only: NO tcgen05) ----------------
__device__ __forceinline__ uint32_t smem_u32(const void* p) {
    uint32_t a;
    asm("{ .reg .u64 t; cvta.to.shared.u64 t, %1; cvt.u32.u64 %0, t; }" : "=r"(a) : "l"(p));
    return a;
}
__device__ __forceinline__ void cpasync16(uint32_t dst, const void* src) {
    asm volatile("cp.async.cg.shared.global [%0], [%1], 16;" :: "r"(dst), "l"(src));
}
__device__ __forceinline__ void cp_commit() { asm volatile("cp.async.commit_group;" ::: "memory"); }
__device__ __forceinline__ void cp_wait1()  { asm volatile("cp.async.wait_group 1;" ::: "memory"); }
__device__ __forceinline__ void cp_wait0()  { asm volatile("cp.async.wait_group 0;" ::: "memory"); }

#define LDSM_X4(r0, r1, r2, r3, addr)                                          \
    asm volatile("ldmatrix.sync.aligned.m8n8.x4.shared.b16 {%0,%1,%2,%3}, [%4];" \
        : "=r"(r0), "=r"(r1), "=r"(r2), "=r"(r3) : "r"(addr))

#define MMA16816(c, a0, a1, a2, a3, b0, b1)                                    \
    asm volatile("mma.sync.aligned.m16n8k16.row.col.f32.bf16.bf16.f32 "        \
        "{%0,%1,%2,%3}, {%4,%5,%6,%7}, {%8,%9}, {%0,%1,%2,%3};"                \
        : "+f"((c)[0]), "+f"((c)[1]), "+f"((c)[2]), "+f"((c)[3])               \
        : "r"(a0), "r"(a1), "r"(a2), "r"(a3), "r"(b0), "r"(b1))

// ---------------- quantization prep ----------------
__global__ void zero_max_kernel() {
    if (threadIdx.x < 3) g_maxbits[threadIdx.x] = 0u;
}

__global__ void maxabs_kernel(const float* __restrict__ W, int n, int slot) {
    unsigned m = 0u;
    for (int i = blockIdx.x*blockDim.x + threadIdx.x; i < n; i += gridDim.x*blockDim.x)
        m = max(m, __float_as_uint(fabsf(W[i])));
    #pragma unroll
    for (int o = 16; o; o >>= 1) m = max(m, __shfl_xor_sync(0xffffffffu, m, o));
    __shared__ unsigned sm[32];
    int lane = threadIdx.x & 31, wid = threadIdx.x >> 5;
    if (lane == 0) sm[wid] = m;
    __syncthreads();
    if (wid == 0) {
        m = (lane < (int)(blockDim.x >> 5)) ? sm[lane] : 0u;
        #pragma unroll
        for (int o = 16; o; o >>= 1) m = max(m, __shfl_xor_sync(0xffffffffu, m, o));
        if (lane == 0) atomicMax(&g_maxbits[slot], m);
    }
}

__device__ __forceinline__ float qwr(float w, float s) {   // integer part only
    float r = rintf(__fdiv_rn(w, s));
    return fminf(fmaxf(r, -127.0f), 127.0f);
}
__device__ __forceinline__ float qb(float b, float s) {
    float r = rintf(__fdiv_rn(b, s));
    r = fminf(fmaxf(r, -128.0f), 127.0f);
    return r * s;
}

__global__ void quant_all_kernel(const float* __restrict__ W1, const float* __restrict__ b1,
                                 const float* __restrict__ W2, const float* __restrict__ b2,
                                 const float* __restrict__ W3, const float* __restrict__ b3,
                                 float s_in) {
    const float ws1 = __fdiv_rn(__uint_as_float(g_maxbits[0]), 127.0f);
    const float ws2 = __fdiv_rn(__uint_as_float(g_maxbits[1]), 127.0f);
    const float ws3 = __fdiv_rn(__uint_as_float(g_maxbits[2]), 127.0f);
    const float sb1 = s_in * ws1;
    const float sb2 = sb1 * ws2;
    const float sb3 = sb2 * ws3;
    const int tid = blockIdx.x*blockDim.x + threadIdx.x;
    const int stride = gridDim.x*blockDim.x;
    if (tid == 0) { g_scales[0] = ws1; g_scales[1] = ws2; g_scales[2] = ws3; }
    for (int i = tid; i < H1D*OBS;  i += stride) g_W1r[i] = __float2bfloat16(qwr(W1[i], ws1));
    for (int i = tid; i < H2D*H1D;  i += stride) g_W2r[i] = __float2bfloat16(qwr(W2[i], ws2));
    for (int i = tid; i < NOUT*H2D; i += stride) g_W3r[i] = __float2bfloat16(qwr(W3[i], ws3));
    for (int i = tid; i < H1D;  i += stride) g_b1q[i] = qb(b1[i], sb1);
    for (int i = tid; i < H2D;  i += stride) g_b2q[i] = qb(b2[i], sb2);
    for (int i = tid; i < NOUT; i += stride) g_b3q[i] = qb(b3[i], sb3);
}

// ---------------- input conversion: x = obs * s_in^2, split into hi/lo bf16 ----------------
__global__ void conv_x_kernel(const float* __restrict__ obs) {
    const float F0 = (float)((1.0/12000.0) * (1.0/12000.0));
    const size_t n2 = (size_t)B_ROWS * OBS / 2;
    for (size_t i = (size_t)blockIdx.x*blockDim.x + threadIdx.x; i < n2;
         i += (size_t)gridDim.x*blockDim.x) {
        float2 v = ((const float2*)obs)[i];
        float a = v.x * F0, b = v.y * F0;
        __nv_bfloat16 ah = __float2bfloat16(a), bh = __float2bfloat16(b);
        __nv_bfloat162 ph; ph.x = ah; ph.y = bh;
        ((__nv_bfloat162*)g_xhi)[i] = ph;
        __nv_bfloat162 pl;
        pl.x = __float2bfloat16(a - __bfloat162float(ah));
        pl.y = __float2bfloat16(b - __bfloat162float(bh));
        ((__nv_bfloat162*)g_xlo)[i] = pl;
    }
}

// ---------------- HMMA GEMM ----------------
// D[128,128] per CTA = (Ahi+Alo)[M,K] @ Wr[N,K]^T ; epilogue: *ws + bias (+relu, hi/lo split)
// 8 warps: 2(M) x 4(N); warp tile 64x32 via mma.m16n8k16 (4 m-tiles x 4 n-tiles).
// K in chunks of 64 bf16 (128B rows, XOR-16B swizzle), cp.async double-buffered.
#define BK 64
#define ASTG (128*BK*2)          // 16 KB per A buffer (hi or lo)
#define STG  (3*ASTG)            // Ahi + Alo + B per stage = 48 KB

template<bool SPLIT_RELU>
__global__ __launch_bounds__(256, 1)
void gemm_mma(const __nv_bfloat16* __restrict__ Ahi, const __nv_bfloat16* __restrict__ Alo,
              const __nv_bfloat16* __restrict__ Br,  const float* __restrict__ bias,
              int K, int Nd, int sIdx,
              __nv_bfloat16* __restrict__ oHi, __nv_bfloat16* __restrict__ oLo,
              float* __restrict__ oF) {
    extern __shared__ __align__(128) char smem[];
    const uint32_t sb = smem_u32(smem);
    const int tid = threadIdx.x, wid = tid >> 5, lane = tid & 31;
    const int bm = blockIdx.y * 128, bn = blockIdx.x * 128;
    const int wm = wid >> 2, wn = wid & 3;           // 2 x 4 warps

    float acc[4][4][4];
    #pragma unroll
    for (int i = 0; i < 4; i++)
        #pragma unroll
        for (int j = 0; j < 4; j++)
            #pragma unroll
            for (int v = 0; v < 4; v++) acc[i][j][v] = 0.0f;

    // loader mapping: 1024 16B-chunks per sub-tile, 4 per thread
    const int lr = tid >> 3;          // rows step 32... (idx/8 below)
    const int lc = tid & 7;
    (void)lr; (void)lc;

    const int nIter = K >> 6;

    auto load_stage = [&](int i) {
        const int b = i & 1;
        const uint32_t s0 = sb + b * STG;
        const int k0 = i << 6;
        #pragma unroll
        for (int o = 0; o < 4; o++) {
            int idx = tid + o * 256;
            int r = idx >> 3, c = idx & 7;
            uint32_t soff = (uint32_t)(r * 128 + ((c ^ (r & 7)) << 4));
            size_t goff = (size_t)(bm + r) * K + k0 + c * 8;
            cpasync16(s0 + soff, Ahi + goff);
            cpasync16(s0 + ASTG + soff, Alo + goff);
            cpasync16(s0 + 2 * ASTG + soff, Br + (size_t)(bn + r) * K + k0 + c * 8);
        }
        cp_commit();
    };

    // per-thread ldmatrix row/group decomposition
    const int g  = lane >> 3;         // 0..3
    const int glr = lane & 7;         // 0..7
    // A x4: row = base + (g&1)*8 + glr ; chunk = c0 + (g>>1)
    const int arow = (g & 1) * 8 + glr;
    const int ach  = g >> 1;
    // B x4: row = base + (g>>1)*8 + glr ; chunk = c0 + (g&1)
    const int brow = (g >> 1) * 8 + glr;
    const int bch  = g & 1;

    load_stage(0);

    for (int i = 0; i < nIter; ++i) {
        if (i + 1 < nIter) { load_stage(i + 1); cp_wait1(); }
        else               { cp_wait0(); }
        __syncthreads();

        const uint32_t s0 = sb + (i & 1) * STG;
        #pragma unroll
        for (int ks = 0; ks < 4; ks++) {
            const int c0 = ks * 2;
            // B fragments: 4 n-tiles (2 ldmatrix.x4)
            uint32_t bf[4][2];
            #pragma unroll
            for (int nt2 = 0; nt2 < 2; nt2++) {
                int row = wn * 32 + nt2 * 16 + brow;
                uint32_t addr = s0 + 2 * ASTG + row * 128 + (((c0 + bch) ^ (row & 7)) << 4);
                LDSM_X4(bf[2*nt2][0], bf[2*nt2][1], bf[2*nt2+1][0], bf[2*nt2+1][1], addr);
            }
            // A hi fragments + MMA
            uint32_t af[4][4];
            #pragma unroll
            for (int mt = 0; mt < 4; mt++) {
                int row = wm * 64 + mt * 16 + arow;
                uint32_t addr = s0 + row * 128 + (((c0 + ach) ^ (row & 7)) << 4);
                LDSM_X4(af[mt][0], af[mt][1], af[mt][2], af[mt][3], addr);
            }
            #pragma unroll
            for (int mt = 0; mt < 4; mt++)
                #pragma unroll
                for (int nt = 0; nt < 4; nt++)
                    MMA16816(acc[mt][nt], af[mt][0], af[mt][1], af[mt][2], af[mt][3],
                             bf[nt][0], bf[nt][1]);
            // A lo fragments + MMA
            #pragma unroll
            for (int mt = 0; mt < 4; mt++) {
                int row = wm * 64 + mt * 16 + arow;
                uint32_t addr = s0 + ASTG + row * 128 + (((c0 + ach) ^ (row & 7)) << 4);
                LDSM_X4(af[mt][0], af[mt][1], af[mt][2], af[mt][3], addr);
            }
            #pragma unroll
            for (int mt = 0; mt < 4; mt++)
                #pragma unroll
                for (int nt = 0; nt < 4; nt++)
                    MMA16816(acc[mt][nt], af[mt][0], af[mt][1], af[mt][2], af[mt][3],
                             bf[nt][0], bf[nt][1]);
        }
        __syncthreads();
    }

    // ---- epilogue: acc fragment (t/4 = row-in-8, t%4*2 = col pair) ----
    const float ws = g_scales[sIdx];
    const int qr = lane >> 2;         // 0..7
    const int qc = (lane & 3) * 2;    // 0,2,4,6
    #pragma unroll
    for (int mt = 0; mt < 4; mt++) {
        #pragma unroll
        for (int nt = 0; nt < 4; nt++) {
            int col = bn + wn * 32 + nt * 8 + qc;
            float bs0 = __ldg(&bias[col]), bs1 = __ldg(&bias[col + 1]);
            #pragma unroll
            for (int h = 0; h < 2; h++) {          // h=0: rows +0..7, h=1: rows +8..15
                size_t row = (size_t)(bm + wm * 64 + mt * 16 + qr + h * 8);
                float o0 = fmaf(acc[mt][nt][2*h + 0], ws, bs0);
                float o1 = fmaf(acc[mt][nt][2*h + 1], ws, bs1);
                if (SPLIT_RELU) {
                    o0 = fmaxf(o0, 0.0f);
                    o1 = fmaxf(o1, 0.0f);
                    __nv_bfloat16 h0 = __float2bfloat16(o0), h1 = __float2bfloat16(o1);
                    __nv_bfloat162 phv; phv.x = h0; phv.y = h1;
                    *reinterpret_cast<__nv_bfloat162*>(oHi + row * Nd + col) = phv;
                    __nv_bfloat162 plv;
                    plv.x = __float2bfloat16(o0 - __bfloat162float(h0));
                    plv.y = __float2bfloat16(o1 - __bfloat162float(h1));
                    *reinterpret_cast<__nv_bfloat162*>(oLo + row * Nd + col) = plv;
                } else {
                    float2 fo; fo.x = o0; fo.y = o1;
                    *reinterpret_cast<float2*>(oF + row * Nd + col) = fo;
                }
            }
        }
    }
}

// ---------------- distribution epilogue: one warp per batch row ----------------
__global__ void epilogue_kernel(const float* __restrict__ eps,
                                const float* __restrict__ net_in,
                                float* __restrict__ outAction,
                                float* __restrict__ outLogp) {
    const int row  = blockIdx.x * (blockDim.x >> 5) + (threadIdx.x >> 5);
    const int lane = threadIdx.x & 31;
    if (row >= B_ROWS) return;
    const float* net = net_in + (size_t)row * NOUT;
    float s = 0.0f;
    #pragma unroll
    for (int h = 0; h < 2; h++) {
        int j = lane + h*32;
        float mu = net[j];
        float ls = fminf(fmaxf(net[ACT + j], -20.0f), 2.0f);
        float sd = expf(ls);
        float e  = eps[(size_t)row*ACT + j];
        float pi = fmaf(sd, e, mu);
        outAction[(size_t)row*ACT + j] = tanhf(pi);
        float z  = (pi - mu) / sd;
        float m2p = -2.0f * pi;
        float sp  = fmaxf(m2p, 0.0f) + log1pf(expf(-fabsf(m2p)));  // softplus(-2*pi)
        s += -0.5f*z*z - ls - 0.91893853320467274f
             - 2.0f*(0.69314718055994531f - pi - sp);
    }
    #pragma unroll
    for (int o = 16; o; o >>= 1) s += __shfl_xor_sync(0xffffffffu, s, o);
    if (lane == 0 && outLogp) outLogp[row] = s;
}

// ---------------- launcher ----------------
extern "C" void kernel_launch(void* const* d_in, const int* in_sizes, int n_in,
                              void* d_out, int out_size) {
    const float* obs = (const float*)d_in[0];
    const float* eps = (const float*)d_in[1];
    const float* W1  = (const float*)d_in[2];
    const float* b1  = (const float*)d_in[3];
    const float* W2  = (const float*)d_in[4];
    const float* b2  = (const float*)d_in[5];
    const float* W3  = (const float*)d_in[6];
    const float* b3  = (const float*)d_in[7];

    float* out = (float*)d_out;
    float* outAction = out;
    float* outLogp = (out_size >= B_ROWS*(ACT+1)) ? (out + (size_t)B_ROWS*ACT) : nullptr;

    const float S_IN = (float)(1.0/12000.0);

    __nv_bfloat16 *pW1r, *pW2r, *pW3r, *pxhi, *pxlo, *ph1hi, *ph1lo, *ph2hi, *ph2lo;
    float *pb1q, *pb2q, *pb3q, *pnet;
    cudaGetSymbolAddress((void**)&pW1r, g_W1r);
    cudaGetSymbolAddress((void**)&pW2r, g_W2r);
    cudaGetSymbolAddress((void**)&pW3r, g_W3r);
    cudaGetSymbolAddress((void**)&pb1q, g_b1q);
    cudaGetSymbolAddress((void**)&pb2q, g_b2q);
    cudaGetSymbolAddress((void**)&pb3q, g_b3q);
    cudaGetSymbolAddress((void**)&pxhi, g_xhi);
    cudaGetSymbolAddress((void**)&pxlo, g_xlo);
    cudaGetSymbolAddress((void**)&ph1hi, g_h1hi);
    cudaGetSymbolAddress((void**)&ph1lo, g_h1lo);
    cudaGetSymbolAddress((void**)&ph2hi, g_h2hi);
    cudaGetSymbolAddress((void**)&ph2lo, g_h2lo);
    cudaGetSymbolAddress((void**)&pnet, g_net);

    const int SMEM = 2 * STG;   // 98304
    cudaFuncSetAttribute(gemm_mma<true>,  cudaFuncAttributeMaxDynamicSharedMemorySize, SMEM);
    cudaFuncSetAttribute(gemm_mma<false>, cudaFuncAttributeMaxDynamicSharedMemorySize, SMEM);

    // 1) quantization prep
    zero_max_kernel<<<1, 32>>>();
    maxabs_kernel<<<256, 256>>>(W1, H1D*OBS, 0);
    maxabs_kernel<<<256, 256>>>(W2, H2D*H1D, 1);
    maxabs_kernel<<<64,  256>>>(W3, NOUT*H2D, 2);
    quant_all_kernel<<<512, 256>>>(W1, b1, W2, b2, W3, b3, S_IN);

    // 2) input split
    conv_x_kernel<<<2048, 256>>>(obs);

    // 3) MLP on tensor cores (register HMMA)
    dim3 g1(H1D/128, B_ROWS/128);
    gemm_mma<true><<<g1, 256, SMEM>>>(pxhi, pxlo, pW1r, pb1q, OBS, H1D, 0,
                                      ph1hi, ph1lo, nullptr);
    dim3 g2(H2D/128, B_ROWS/128);
    gemm_mma<true><<<g2, 256, SMEM>>>(ph1hi, ph1lo, pW2r, pb2q, H1D, H2D, 1,
                                      ph2hi, ph2lo, nullptr);
    dim3 g3(NOUT/128, B_ROWS/128);
    gemm_mma<false><<<g3, 256, SMEM>>>(ph2hi, ph2lo, pW3r, pb3q, H2D, NOUT, 2,
                                       nullptr, nullptr, pnet);

    // 4) squashed-Gaussian epilogue
    epilogue_kernel<<<B_ROWS/8, 256>>>(eps, pnet, outAction, outLogp);
}

// round 6
// speedup vs baseline: 5.9125x; 1.7647x over previous
#include <cuda_runtime.h>
#include <cuda_bf16.h>
#include <math.h>
#include <stdint.h>

#define B_ROWS 32768
#define OBS    512
#define H1D    1024
#define H2D    1024
#define ACT    64
#define NOUT   (2*ACT)

// ---------------- device scratch (static: no allocations allowed) ----------------
__device__ __nv_bfloat16 g_W1r[H1D*OBS];     // integer-valued bf16 weights (exact)
__device__ __nv_bfloat16 g_W2r[H2D*H1D];
__device__ __nv_bfloat16 g_W3r[NOUT*H2D];
__device__ float g_b1q[H1D];
__device__ float g_b2q[H2D];
__device__ float g_b3q[NOUT];
__device__ float g_scales[3];
__device__ unsigned g_maxbits[3];
__device__ __nv_bfloat16 g_x[(size_t)B_ROWS*OBS];
__device__ __nv_bfloat16 g_h1[(size_t)B_ROWS*H1D];
__device__ __nv_bfloat16 g_h2[(size_t)B_ROWS*H2D];
__device__ float g_net[(size_t)B_ROWS*NOUT];

// ---------------- PTX helpers (sm_103-safe subset only) ----------------
__device__ __forceinline__ uint32_t smem_u32(const void* p) {
    uint32_t a;
    asm("{ .reg .u64 t; cvta.to.shared.u64 t, %1; cvt.u32.u64 %0, t; }" : "=r"(a) : "l"(p));
    return a;
}
__device__ __forceinline__ void cpasync16(uint32_t dst, const void* src) {
    asm volatile("cp.async.cg.shared.global [%0], [%1], 16;" :: "r"(dst), "l"(src));
}
__device__ __forceinline__ void cp_commit() { asm volatile("cp.async.commit_group;" ::: "memory"); }
__device__ __forceinline__ void cp_wait2()  { asm volatile("cp.async.wait_group 2;" ::: "memory"); }
__device__ __forceinline__ void cp_wait1()  { asm volatile("cp.async.wait_group 1;" ::: "memory"); }
__device__ __forceinline__ void cp_wait0()  { asm volatile("cp.async.wait_group 0;" ::: "memory"); }

#define LDSM_X4(r0, r1, r2, r3, addr)                                          \
    asm volatile("ldmatrix.sync.aligned.m8n8.x4.shared.b16 {%0,%1,%2,%3}, [%4];" \
        : "=r"(r0), "=r"(r1), "=r"(r2), "=r"(r3) : "r"(addr))

#define MMA16816(c, a0, a1, a2, a3, b0, b1)                                    \
    asm volatile("mma.sync.aligned.m16n8k16.row.col.f32.bf16.bf16.f32 "        \
        "{%0,%1,%2,%3}, {%4,%5,%6,%7}, {%8,%9}, {%0,%1,%2,%3};"                \
        : "+f"((c)[0]), "+f"((c)[1]), "+f"((c)[2]), "+f"((c)[3])               \
        : "r"(a0), "r"(a1), "r"(a2), "r"(a3), "r"(b0), "r"(b1))

// ---------------- quantization prep ----------------
__global__ void zero_max_kernel() {
    if (threadIdx.x < 3) g_maxbits[threadIdx.x] = 0u;
}

__global__ void maxabs_kernel(const float* __restrict__ W, int n, int slot) {
    unsigned m = 0u;
    for (int i = blockIdx.x*blockDim.x + threadIdx.x; i < n; i += gridDim.x*blockDim.x)
        m = max(m, __float_as_uint(fabsf(W[i])));
    #pragma unroll
    for (int o = 16; o; o >>= 1) m = max(m, __shfl_xor_sync(0xffffffffu, m, o));
    __shared__ unsigned sm[32];
    int lane = threadIdx.x & 31, wid = threadIdx.x >> 5;
    if (lane == 0) sm[wid] = m;
    __syncthreads();
    if (wid == 0) {
        m = (lane < (int)(blockDim.x >> 5)) ? sm[lane] : 0u;
        #pragma unroll
        for (int o = 16; o; o >>= 1) m = max(m, __shfl_xor_sync(0xffffffffu, m, o));
        if (lane == 0) atomicMax(&g_maxbits[slot], m);
    }
}

__device__ __forceinline__ float qwr(float w, float s) {   // integer part only (exact in bf16)
    float r = rintf(__fdiv_rn(w, s));
    return fminf(fmaxf(r, -127.0f), 127.0f);
}
__device__ __forceinline__ float qb(float b, float s) {
    float r = rintf(__fdiv_rn(b, s));
    r = fminf(fmaxf(r, -128.0f), 127.0f);
    return r * s;
}

__global__ void quant_all_kernel(const float* __restrict__ W1, const float* __restrict__ b1,
                                 const float* __restrict__ W2, const float* __restrict__ b2,
                                 const float* __restrict__ W3, const float* __restrict__ b3,
                                 float s_in) {
    const float ws1 = __fdiv_rn(__uint_as_float(g_maxbits[0]), 127.0f);
    const float ws2 = __fdiv_rn(__uint_as_float(g_maxbits[1]), 127.0f);
    const float ws3 = __fdiv_rn(__uint_as_float(g_maxbits[2]), 127.0f);
    const float sb1 = s_in * ws1;
    const float sb2 = sb1 * ws2;
    const float sb3 = sb2 * ws3;
    const int tid = blockIdx.x*blockDim.x + threadIdx.x;
    const int stride = gridDim.x*blockDim.x;
    if (tid == 0) { g_scales[0] = ws1; g_scales[1] = ws2; g_scales[2] = ws3; }
    for (int i = tid; i < H1D*OBS;  i += stride) g_W1r[i] = __float2bfloat16(qwr(W1[i], ws1));
    for (int i = tid; i < H2D*H1D;  i += stride) g_W2r[i] = __float2bfloat16(qwr(W2[i], ws2));
    for (int i = tid; i < NOUT*H2D; i += stride) g_W3r[i] = __float2bfloat16(qwr(W3[i], ws3));
    for (int i = tid; i < H1D;  i += stride) g_b1q[i] = qb(b1[i], sb1);
    for (int i = tid; i < H2D;  i += stride) g_b2q[i] = qb(b2[i], sb2);
    for (int i = tid; i < NOUT; i += stride) g_b3q[i] = qb(b3[i], sb3);
}

// ---------------- input conversion: x = obs * s_in^2 as bf16 ----------------
__global__ void conv_x_kernel(const float* __restrict__ obs) {
    const float F0 = (float)((1.0/12000.0) * (1.0/12000.0));
    const size_t n2 = (size_t)B_ROWS * OBS / 2;
    for (size_t i = (size_t)blockIdx.x*blockDim.x + threadIdx.x; i < n2;
         i += (size_t)gridDim.x*blockDim.x) {
        float2 v = ((const float2*)obs)[i];
        __nv_bfloat162 p;
        p.x = __float2bfloat16(v.x * F0);
        p.y = __float2bfloat16(v.y * F0);
        ((__nv_bfloat162*)g_x)[i] = p;
    }
}

// ---------------- HMMA GEMM ----------------
// D[128,NTILE] per CTA = A[M,K] @ Wr[N,K]^T ; epilogue: *ws + bias (+relu -> bf16, else fp32)
// 8 warps: 2(M) x 4(N); warp tile 64 x (NTILE/4). K in BK=64 chunks, 3-stage cp.async ring.
#define BK 64
#define ASTG (128*BK*2)          // 16 KB A per stage

template<int NTILE, bool RELU>
__global__ __launch_bounds__(256, 1)
void gemm_mma(const __nv_bfloat16* __restrict__ A,
              const __nv_bfloat16* __restrict__ Br,  const float* __restrict__ bias,
              int K, int Nd, int sIdx,
              __nv_bfloat16* __restrict__ oH, float* __restrict__ oF) {
    constexpr int BSTG = NTILE * 128;           // B bytes per stage
    constexpr int STG  = ASTG + BSTG;
    constexpr int NT   = NTILE / 32;            // n-subtiles per warp (8 or 4)
    extern __shared__ __align__(128) char smem[];
    const uint32_t sb = smem_u32(smem);
    const int tid = threadIdx.x, wid = tid >> 5, lane = tid & 31;
    const int bm = blockIdx.y * 128, bn = blockIdx.x * NTILE;
    const int wm = wid >> 2, wn = wid & 3;      // 2 x 4 warps

    float acc[4][NT][4];
    #pragma unroll
    for (int i = 0; i < 4; i++)
        #pragma unroll
        for (int j = 0; j < NT; j++)
            #pragma unroll
            for (int v = 0; v < 4; v++) acc[i][j][v] = 0.0f;

    const int nIter = K >> 6;

    auto load_stage = [&](int i) {
        const uint32_t s0 = sb + (i % 3) * STG;
        const int k0 = i << 6;
        #pragma unroll
        for (int o = 0; o < 4; o++) {                   // A: 128 rows x 8 chunks
            int idx = tid + o * 256;
            int r = idx >> 3, c = idx & 7;
            uint32_t soff = (uint32_t)(r * 128 + ((c ^ (r & 7)) << 4));
            cpasync16(s0 + soff, A + (size_t)(bm + r) * K + k0 + c * 8);
        }
        #pragma unroll
        for (int o = 0; o < NTILE / 32; o++) {          // B: NTILE rows x 8 chunks
            int idx = tid + o * 256;
            int r = idx >> 3, c = idx & 7;
            cpasync16(s0 + ASTG + (uint32_t)(r * 128 + ((c ^ (r & 7)) << 4)),
                      Br + (size_t)(bn + r) * K + k0 + c * 8);
        }
        cp_commit();
    };

    // per-thread ldmatrix row/group decomposition (validated layout)
    const int g  = lane >> 3;
    const int glr = lane & 7;
    const int arow = (g & 1) * 8 + glr;   // A x4: rows pair then chunk pair
    const int ach  = g >> 1;
    const int brow = (g >> 1) * 8 + glr;  // B x4: chunk pair then rows pair
    const int bch  = g & 1;

    load_stage(0);
    if (nIter > 1) load_stage(1);

    for (int i = 0; i < nIter; ++i) {
        if (i + 2 < nIter)      { load_stage(i + 2); cp_wait2(); }
        else if (i + 1 < nIter) { cp_wait1(); }
        else                    { cp_wait0(); }
        __syncthreads();

        const uint32_t s0 = sb + (i % 3) * STG;
        #pragma unroll
        for (int ks = 0; ks < 4; ks++) {
            const int c0 = ks * 2;
            uint32_t bf[NT][2];
            #pragma unroll
            for (int nt2 = 0; nt2 < NT / 2; nt2++) {
                int row = wn * (NTILE / 4) + nt2 * 16 + brow;
                uint32_t addr = s0 + ASTG + row * 128 + (((c0 + bch) ^ (row & 7)) << 4);
                LDSM_X4(bf[2*nt2][0], bf[2*nt2][1], bf[2*nt2+1][0], bf[2*nt2+1][1], addr);
            }
            uint32_t af[4][4];
            #pragma unroll
            for (int mt = 0; mt < 4; mt++) {
                int row = wm * 64 + mt * 16 + arow;
                uint32_t addr = s0 + row * 128 + (((c0 + ach) ^ (row & 7)) << 4);
                LDSM_X4(af[mt][0], af[mt][1], af[mt][2], af[mt][3], addr);
            }
            #pragma unroll
            for (int mt = 0; mt < 4; mt++)
                #pragma unroll
                for (int nt = 0; nt < NT; nt++)
                    MMA16816(acc[mt][nt], af[mt][0], af[mt][1], af[mt][2], af[mt][3],
                             bf[nt][0], bf[nt][1]);
        }
        __syncthreads();
    }

    // ---- epilogue ----
    const float ws = g_scales[sIdx];
    const int qr = lane >> 2;
    const int qc = (lane & 3) * 2;
    #pragma unroll
    for (int mt = 0; mt < 4; mt++) {
        #pragma unroll
        for (int nt = 0; nt < NT; nt++) {
            int col = bn + wn * (NTILE / 4) + nt * 8 + qc;
            float bs0 = __ldg(&bias[col]), bs1 = __ldg(&bias[col + 1]);
            #pragma unroll
            for (int h = 0; h < 2; h++) {
                size_t row = (size_t)(bm + wm * 64 + mt * 16 + qr + h * 8);
                float o0 = fmaf(acc[mt][nt][2*h + 0], ws, bs0);
                float o1 = fmaf(acc[mt][nt][2*h + 1], ws, bs1);
                if (RELU) {
                    __nv_bfloat162 p;
                    p.x = __float2bfloat16(fmaxf(o0, 0.0f));
                    p.y = __float2bfloat16(fmaxf(o1, 0.0f));
                    *reinterpret_cast<__nv_bfloat162*>(oH + row * Nd + col) = p;
                } else {
                    float2 fo; fo.x = o0; fo.y = o1;
                    *reinterpret_cast<float2*>(oF + row * Nd + col) = fo;
                }
            }
        }
    }
}

// ---------------- distribution epilogue: one warp per batch row ----------------
__global__ void epilogue_kernel(const float* __restrict__ eps,
                                const float* __restrict__ net_in,
                                float* __restrict__ outAction,
                                float* __restrict__ outLogp) {
    const int row  = blockIdx.x * (blockDim.x >> 5) + (threadIdx.x >> 5);
    const int lane = threadIdx.x & 31;
    if (row >= B_ROWS) return;
    const float* net = net_in + (size_t)row * NOUT;
    float s = 0.0f;
    #pragma unroll
    for (int h = 0; h < 2; h++) {
        int j = lane + h*32;
        float mu = net[j];
        float ls = fminf(fmaxf(net[ACT + j], -20.0f), 2.0f);
        float sd = expf(ls);
        float e  = eps[(size_t)row*ACT + j];
        float pi = fmaf(sd, e, mu);
        outAction[(size_t)row*ACT + j] = tanhf(pi);
        float z  = (pi - mu) / sd;
        float m2p = -2.0f * pi;
        float sp  = fmaxf(m2p, 0.0f) + log1pf(expf(-fabsf(m2p)));  // softplus(-2*pi)
        s += -0.5f*z*z - ls - 0.91893853320467274f
             - 2.0f*(0.69314718055994531f - pi - sp);
    }
    #pragma unroll
    for (int o = 16; o; o >>= 1) s += __shfl_xor_sync(0xffffffffu, s, o);
    if (lane == 0 && outLogp) outLogp[row] = s;
}

// ---------------- launcher ----------------
extern "C" void kernel_launch(void* const* d_in, const int* in_sizes, int n_in,
                              void* d_out, int out_size) {
    const float* obs = (const float*)d_in[0];
    const float* eps = (const float*)d_in[1];
    const float* W1  = (const float*)d_in[2];
    const float* b1  = (const float*)d_in[3];
    const float* W2  = (const float*)d_in[4];
    const float* b2  = (const float*)d_in[5];
    const float* W3  = (const float*)d_in[6];
    const float* b3  = (const float*)d_in[7];

    float* out = (float*)d_out;
    float* outAction = out;
    float* outLogp = (out_size >= B_ROWS*(ACT+1)) ? (out + (size_t)B_ROWS*ACT) : nullptr;

    const float S_IN = (float)(1.0/12000.0);

    __nv_bfloat16 *pW1r, *pW2r, *pW3r, *px, *ph1, *ph2;
    float *pb1q, *pb2q, *pb3q, *pnet;
    cudaGetSymbolAddress((void**)&pW1r, g_W1r);
    cudaGetSymbolAddress((void**)&pW2r, g_W2r);
    cudaGetSymbolAddress((void**)&pW3r, g_W3r);
    cudaGetSymbolAddress((void**)&pb1q, g_b1q);
    cudaGetSymbolAddress((void**)&pb2q, g_b2q);
    cudaGetSymbolAddress((void**)&pb3q, g_b3q);
    cudaGetSymbolAddress((void**)&px,  g_x);
    cudaGetSymbolAddress((void**)&ph1, g_h1);
    cudaGetSymbolAddress((void**)&ph2, g_h2);
    cudaGetSymbolAddress((void**)&pnet, g_net);

    const int SMEM256 = 3 * (ASTG + 256*128);   // 147456
    const int SMEM128 = 3 * (ASTG + 128*128);   //  98304
    cudaFuncSetAttribute(gemm_mma<256, true>,  cudaFuncAttributeMaxDynamicSharedMemorySize, SMEM256);
    cudaFuncSetAttribute(gemm_mma<128, false>, cudaFuncAttributeMaxDynamicSharedMemorySize, SMEM128);

    // 1) quantization prep
    zero_max_kernel<<<1, 32>>>();
    maxabs_kernel<<<256, 256>>>(W1, H1D*OBS, 0);
    maxabs_kernel<<<256, 256>>>(W2, H2D*H1D, 1);
    maxabs_kernel<<<64,  256>>>(W3, NOUT*H2D, 2);
    quant_all_kernel<<<512, 256>>>(W1, b1, W2, b2, W3, b3, S_IN);

    // 2) input conversion
    conv_x_kernel<<<2048, 256>>>(obs);

    // 3) MLP on tensor cores (register HMMA, single bf16 activations)
    dim3 g1(H1D/256, B_ROWS/128);
    gemm_mma<256, true><<<g1, 256, SMEM256>>>(px, pW1r, pb1q, OBS, H1D, 0, ph1, nullptr);
    dim3 g2(H2D/256, B_ROWS/128);
    gemm_mma<256, true><<<g2, 256, SMEM256>>>(ph1, pW2r, pb2q, H1D, H2D, 1, ph2, nullptr);
    dim3 g3(NOUT/128, B_ROWS/128);
    gemm_mma<128, false><<<g3, 256, SMEM128>>>(ph2, pW3r, pb3q, H2D, NOUT, 2, nullptr, pnet);

    // 4) squashed-Gaussian epilogue
    epilogue_kernel<<<B_ROWS/8, 256>>>(eps, pnet, outAction, outLogp);
}